// round 1
// baseline (speedup 1.0000x reference)
#include <cuda_runtime.h>
#include <math.h>

#define NROWS 8192
#define NHALF 4096
#define DDIM  256
#define BM 64
#define BN 64
#define BK 32
#define NSPLIT 16
#define INV_T 10.0f

// scratch (allocation-free rule: __device__ globals)
__device__ float g_zn[NROWS * DDIM];   // normalized rows, 8 MB
__device__ float g_sumexp[NROWS];      // per-row sum of exp(logit), excl. diag
__device__ float g_pos[NROWS];         // positive-pair logit per row

// ---------------------------------------------------------------------------
// Kernel 1: row L2-normalize (one block per row, 256 threads == D) and
// re-zero g_sumexp (must happen every graph replay).
// ---------------------------------------------------------------------------
__global__ void norm_kernel(const float* __restrict__ zi,
                            const float* __restrict__ zj) {
    int row = blockIdx.x;
    int t = threadIdx.x;
    const float* src = (row < NHALF) ? (zi + (size_t)row * DDIM)
                                     : (zj + (size_t)(row - NHALF) * DDIM);
    float v = src[t];
    float ss = v * v;
    #pragma unroll
    for (int o = 16; o > 0; o >>= 1) ss += __shfl_xor_sync(0xffffffffu, ss, o);
    __shared__ float red[8];
    if ((t & 31) == 0) red[t >> 5] = ss;
    __syncthreads();
    if (t < 32) {
        float s = (t < 8) ? red[t] : 0.0f;
        #pragma unroll
        for (int o = 4; o > 0; o >>= 1) s += __shfl_xor_sync(0xffffffffu, s, o);
        if (t == 0) red[0] = s;
    }
    __syncthreads();
    float norm = fmaxf(sqrtf(red[0]), 1e-8f);
    g_zn[(size_t)row * DDIM + t] = v / norm;
    if (t == 0) g_sumexp[row] = 0.0f;
}

// ---------------------------------------------------------------------------
// Kernel 2: fused Gram + streaming sum-exp.
// Grid: (NROWS/BM, NSPLIT). 256 threads, 4x4 microtile -> 64x64 CTA tile.
// A tile (64 rows x full K=256) resident in smem, transposed + XOR-swizzled
// (vec4 granularity): reads are half-warp broadcasts (A) / contiguous vec4 (B).
// Smem: A 64KB + B 8KB = 72KB dynamic.
// ---------------------------------------------------------------------------
__global__ void __launch_bounds__(256, 2) simloss_kernel() {
    extern __shared__ float4 dynsmem[];
    float4* As4 = dynsmem;                 // [256][16] vec4
    float4* Bs4 = dynsmem + 256 * 16;      // [32][16]  vec4

    int t = threadIdx.x;
    int tx = t & 15;
    int ty = t >> 4;
    int rowBase = blockIdx.x * BM;
    const int tilesPerSplit = NROWS / BN / NSPLIT;    // 8
    int tileBeg = blockIdx.y * tilesPerSplit;
    int tileEnd = tileBeg + tilesPerSplit;

    const float4* zn4 = (const float4*)g_zn;          // row stride = 64 vec4

    // Load A tile: 64 rows x 256 K, transposed into As4[k][*] with swizzle.
    // element (k, r) lives at float offset k*64 + ((r>>2)^(k&15))*4 + (r&3)
    for (int v = t; v < 64 * 64; v += 256) {
        int r  = v >> 6;       // 0..63
        int kv = v & 63;       // vec4 index along K
        float4 val = zn4[(size_t)(rowBase + r) * 64 + kv];
        int c4 = r >> 2, lane = r & 3;
        float vv[4] = {val.x, val.y, val.z, val.w};
        #pragma unroll
        for (int j = 0; j < 4; j++) {
            int k = kv * 4 + j;
            ((float*)&As4[(k << 4) + (c4 ^ (k & 15))])[lane] = vv[j];
        }
    }

    float rowsum[4] = {0.f, 0.f, 0.f, 0.f};

    for (int tile = tileBeg; tile < tileEnd; tile++) {
        int colBase = tile * BN;
        float acc[4][4] = {};
        for (int k0 = 0; k0 < DDIM; k0 += BK) {
            __syncthreads();   // protects Bs reuse (and covers A-load on iter 0)
            #pragma unroll
            for (int i = 0; i < 2; i++) {
                int v  = t + i * 256;      // 0..511
                int c  = v >> 3;           // 0..63
                int kv = v & 7;            // vec4 within BK
                float4 val = zn4[(size_t)(colBase + c) * 64 + (k0 >> 2) + kv];
                int c4 = c >> 2, lane = c & 3;
                float vv[4] = {val.x, val.y, val.z, val.w};
                #pragma unroll
                for (int j = 0; j < 4; j++) {
                    int k = kv * 4 + j;
                    ((float*)&Bs4[(k << 4) + (c4 ^ (k & 15))])[lane] = vv[j];
                }
            }
            __syncthreads();

            #pragma unroll
            for (int kk = 0; kk < BK; kk++) {
                int kg = k0 + kk;
                float4 a4 = As4[(kg << 4) + (ty ^ (kg & 15))];
                float4 b4 = Bs4[(kk << 4) + (tx ^ (kk & 15))];
                float av[4] = {a4.x, a4.y, a4.z, a4.w};
                float bv[4] = {b4.x, b4.y, b4.z, b4.w};
                #pragma unroll
                for (int m = 0; m < 4; m++)
                    #pragma unroll
                    for (int n = 0; n < 4; n++)
                        acc[m][n] = fmaf(av[m], bv[n], acc[m][n]);
            }
        }

        // epilogue: logits -> exp-sum, positive capture, diag skip
        #pragma unroll
        for (int m = 0; m < 4; m++) {
            int gi = rowBase + ty * 4 + m;
            #pragma unroll
            for (int n = 0; n < 4; n++) {
                int gj = colBase + tx * 4 + n;
                float logit = acc[m][n] * INV_T;
                if (gj == (gi ^ NHALF)) g_pos[gi] = logit;
                if (gj != gi) rowsum[m] += __expf(logit);
            }
        }
    }

    // reduce across the 16 tx lanes (stays inside half-warp), one atomic/row
    #pragma unroll
    for (int m = 0; m < 4; m++) {
        float s = rowsum[m];
        #pragma unroll
        for (int o = 8; o > 0; o >>= 1) s += __shfl_xor_sync(0xffffffffu, s, o);
        if (tx == 0) atomicAdd(&g_sumexp[rowBase + ty * 4 + m], s);
    }
}

// ---------------------------------------------------------------------------
// Kernel 3: mean(log(sumexp) - pos_logit)
// ---------------------------------------------------------------------------
__global__ void finalize_kernel(float* __restrict__ out) {
    int t = threadIdx.x;
    float acc = 0.0f;
    for (int r = t; r < NROWS; r += 256)
        acc += logf(g_sumexp[r]) - g_pos[r];
    #pragma unroll
    for (int o = 16; o > 0; o >>= 1) acc += __shfl_xor_sync(0xffffffffu, acc, o);
    __shared__ float red[8];
    if ((t & 31) == 0) red[t >> 5] = acc;
    __syncthreads();
    if (t == 0) {
        float s = 0.0f;
        #pragma unroll
        for (int i = 0; i < 8; i++) s += red[i];
        out[0] = s / (float)NROWS;
    }
}

// ---------------------------------------------------------------------------
extern "C" void kernel_launch(void* const* d_in, const int* in_sizes, int n_in,
                              void* d_out, int out_size) {
    const float* zi = (const float*)d_in[0];
    const float* zj = (const float*)d_in[1];
    float* out = (float*)d_out;

    // 72KB dynamic smem > 48KB static limit; attribute set is idempotent,
    // not a stream op, safe under graph capture.
    cudaFuncSetAttribute(simloss_kernel,
                         cudaFuncAttributeMaxDynamicSharedMemorySize,
                         (256 * 16 + 32 * 16) * (int)sizeof(float4));

    norm_kernel<<<NROWS, 256>>>(zi, zj);
    dim3 grid(NROWS / BM, NSPLIT);
    simloss_kernel<<<grid, 256, (256 * 16 + 32 * 16) * sizeof(float4)>>>();
    finalize_kernel<<<1, 256>>>(out);
}

// round 3
// speedup vs baseline: 11.6130x; 11.6130x over previous
#include <cuda_runtime.h>
#include <cuda_bf16.h>
#include <stdint.h>
#include <math.h>

#define NROWS 8192
#define NHALF 4096
#define DDIM  256
#define TM 128
#define TN 128
#define KC 64
#define NK (DDIM / KC)                 // 4 k-chunks
#define NTILE (NROWS / TM)             // 64
#define NCTA (NTILE * (NTILE + 1) / 2) // 2080 upper-triangle tiles
#define STRIDEW 36                     // smem words per tile row (32 data + 4 pad)
#define TILEW (128 * STRIDEW)          // 4608 words per operand buffer
#define INV_T 10.0f

// scratch (allocation-free rule: __device__ globals)
__device__ __align__(16) __nv_bfloat16 g_znh[NROWS * DDIM]; // normalized rows, bf16 (4 MB)
__device__ float g_sumexp[NROWS];
__device__ float g_pos[NROWS];

__device__ __forceinline__ void cp16(uint32_t s, const void* g) {
    asm volatile("cp.async.cg.shared.global [%0], [%1], 16;\n" :: "r"(s), "l"(g));
}
__device__ __forceinline__ void cp_commit() { asm volatile("cp.async.commit_group;\n" ::: "memory"); }
__device__ __forceinline__ void cp_wait0()  { asm volatile("cp.async.wait_group 0;\n" ::: "memory"); }

__device__ __forceinline__ void mma16816(float* c, const uint32_t* a, const uint32_t* b) {
    asm volatile(
        "mma.sync.aligned.m16n8k16.row.col.f32.bf16.bf16.f32 "
        "{%0,%1,%2,%3}, {%4,%5,%6,%7}, {%8,%9}, {%0,%1,%2,%3};\n"
        : "+f"(c[0]), "+f"(c[1]), "+f"(c[2]), "+f"(c[3])
        : "r"(a[0]), "r"(a[1]), "r"(a[2]), "r"(a[3]), "r"(b[0]), "r"(b[1]));
}

// ---------------------------------------------------------------------------
// Kernel 1: L2-normalize (fp32 math), emit bf16 rows; re-zero g_sumexp each
// replay. One warp per row, float4 loads, bf16x2 stores.
// ---------------------------------------------------------------------------
__global__ void norm_kernel(const float* __restrict__ zi,
                            const float* __restrict__ zj) {
    int warp = threadIdx.x >> 5, lane = threadIdx.x & 31;
    int row = blockIdx.x * 8 + warp;
    const float* srcf = (row < NHALF) ? (zi + (size_t)row * DDIM)
                                      : (zj + (size_t)(row - NHALF) * DDIM);
    const float4* src = (const float4*)srcf;
    float4 a = src[lane];
    float4 b = src[lane + 32];
    float ss = a.x*a.x + a.y*a.y + a.z*a.z + a.w*a.w
             + b.x*b.x + b.y*b.y + b.z*b.z + b.w*b.w;
    #pragma unroll
    for (int o = 16; o > 0; o >>= 1) ss += __shfl_xor_sync(0xffffffffu, ss, o);
    float inv = 1.0f / fmaxf(sqrtf(ss), 1e-8f);

    __nv_bfloat162* out = (__nv_bfloat162*)(g_znh + (size_t)row * DDIM);
    out[lane * 2 + 0]      = __floats2bfloat162_rn(a.x * inv, a.y * inv);
    out[lane * 2 + 1]      = __floats2bfloat162_rn(a.z * inv, a.w * inv);
    out[64 + lane * 2 + 0] = __floats2bfloat162_rn(b.x * inv, b.y * inv);
    out[64 + lane * 2 + 1] = __floats2bfloat162_rn(b.z * inv, b.w * inv);
    if (lane == 0) g_sumexp[row] = 0.0f;
}

// ---------------------------------------------------------------------------
// Kernel 2: upper-triangular Gram via bf16 mma.sync, fused exp row+col sums.
// 2080 CTAs (one per tile pair I<=J), 256 threads, 8 warps as 2(m) x 4(n),
// each warp 64x32 via 4x4 grid of m16n8k16 fragments.
// Smem: A/B double-buffered (4 x 18KB, stride-36 padded => conflict-free
// fragment LDS: bank = 4*g + c = lane) + 256-float reduction arrays.
// ---------------------------------------------------------------------------
__global__ void __launch_bounds__(256, 2) gram_kernel() {
    extern __shared__ uint32_t sm[];
    float* rowS = (float*)(sm + 4 * TILEW);
    float* colS = rowS + TM;

    int t = threadIdx.x;
    int bid = blockIdx.x;

    // upper-triangle tile index: row I has (NTILE - I) tiles
    int I = 0;
    while (NTILE * (I + 1) - ((I + 1) * I) / 2 <= bid) I++;
    int J = I + (bid - (NTILE * I - (I * (I - 1)) / 2));
    int rowBase = I * TM, colBase = J * TN;

    if (t < TM) { rowS[t] = 0.0f; colS[t] = 0.0f; }

    int lane = t & 31;
    int g = lane >> 2, c = lane & 3;
    int warp = t >> 5;
    int wm = warp & 1;        // 0..1 (m)
    int wn = warp >> 1;       // 0..3 (n)

    const char* gbase = (const char*)g_znh;
    uint32_t smbase = (uint32_t)__cvta_generic_to_shared(sm);

    auto prefetch = [&](int kc, int buf) {
        uint32_t sA = smbase + (uint32_t)(buf * TILEW) * 4u;
        uint32_t sB = smbase + (uint32_t)((2 + buf) * TILEW) * 4u;
        #pragma unroll
        for (int i = 0; i < 4; i++) {
            int idx = t + i * 256;         // 0..1023
            int r = idx >> 3, seg = idx & 7;
            uint32_t soff = (uint32_t)(r * STRIDEW + seg * 4) * 4u;
            size_t gA = ((size_t)(rowBase + r) * DDIM + kc * KC + seg * 8) * 2;
            size_t gB = ((size_t)(colBase + r) * DDIM + kc * KC + seg * 8) * 2;
            cp16(sA + soff, gbase + gA);
            cp16(sB + soff, gbase + gB);
        }
    };

    float acc[4][4][4] = {};

    prefetch(0, 0);
    cp_commit();

    #pragma unroll
    for (int kc = 0; kc < NK; kc++) {
        cp_wait0();
        __syncthreads();
        if (kc + 1 < NK) { prefetch(kc + 1, (kc + 1) & 1); cp_commit(); }

        const uint32_t* As = sm + (kc & 1) * TILEW;
        const uint32_t* Bs = sm + (2 + (kc & 1)) * TILEW;

        #pragma unroll
        for (int ks = 0; ks < KC / 16; ks++) {
            uint32_t a[4][4], b[4][2];
            int w0 = ks * 8 + c;
            #pragma unroll
            for (int mt = 0; mt < 4; mt++) {
                int r0 = wm * 64 + mt * 16 + g;
                a[mt][0] = As[r0 * STRIDEW + w0];
                a[mt][1] = As[(r0 + 8) * STRIDEW + w0];
                a[mt][2] = As[r0 * STRIDEW + w0 + 4];
                a[mt][3] = As[(r0 + 8) * STRIDEW + w0 + 4];
            }
            #pragma unroll
            for (int nt = 0; nt < 4; nt++) {
                int n0 = wn * 32 + nt * 8 + g;
                b[nt][0] = Bs[n0 * STRIDEW + w0];
                b[nt][1] = Bs[n0 * STRIDEW + w0 + 4];
            }
            #pragma unroll
            for (int mt = 0; mt < 4; mt++)
                #pragma unroll
                for (int nt = 0; nt < 4; nt++)
                    mma16816(acc[mt][nt], a[mt], b[nt]);
        }
    }

    // ---- epilogue: logits -> exp, diag mask, positive capture, row/col sums
    float rloc[4][2] = {};   // per (mt, row-half): sum over this thread's 8 cols
    float cloc[4][2] = {};   // per (nt, col-in-pair): sum over this thread's 8 rows
    bool isPosTile = (colBase == (rowBase ^ NHALF));

    #pragma unroll
    for (int mt = 0; mt < 4; mt++) {
        #pragma unroll
        for (int h = 0; h < 2; h++) {
            int rl = wm * 64 + mt * 16 + g + 8 * h;
            int gi = rowBase + rl;
            #pragma unroll
            for (int nt = 0; nt < 4; nt++) {
                #pragma unroll
                for (int j = 0; j < 2; j++) {
                    int cl = wn * 32 + nt * 8 + 2 * c + j;
                    int gj = colBase + cl;
                    // c-fragment layout: idx = 2*h + j
                    float logit = acc[mt][nt][2 * h + j] * INV_T;
                    if (isPosTile && cl == rl) { g_pos[gi] = logit; g_pos[gj] = logit; }
                    float e = (gi == gj) ? 0.0f : __expf(logit);
                    rloc[mt][h] += e;
                    cloc[nt][j] += e;
                }
            }
        }
    }

    // row sums: reduce across the 4 lanes sharing g (lane^1, lane^2)
    #pragma unroll
    for (int mt = 0; mt < 4; mt++) {
        #pragma unroll
        for (int h = 0; h < 2; h++) {
            float v = rloc[mt][h];
            v += __shfl_xor_sync(0xffffffffu, v, 1);
            v += __shfl_xor_sync(0xffffffffu, v, 2);
            if (c == 0) atomicAdd(&rowS[wm * 64 + mt * 16 + g + 8 * h], v);
        }
    }
    // col sums: reduce across the 8 lanes sharing c (lane^4, ^8, ^16)
    #pragma unroll
    for (int nt = 0; nt < 4; nt++) {
        #pragma unroll
        for (int j = 0; j < 2; j++) {
            float v = cloc[nt][j];
            v += __shfl_xor_sync(0xffffffffu, v, 4);
            v += __shfl_xor_sync(0xffffffffu, v, 8);
            v += __shfl_xor_sync(0xffffffffu, v, 16);
            if (g == 0) atomicAdd(&colS[wn * 32 + nt * 8 + 2 * c + j], v);
        }
    }

    __syncthreads();
    if (t < TM) {
        atomicAdd(&g_sumexp[rowBase + t], rowS[t]);
        if (rowBase != colBase)                          // diag tile: rows only
            atomicAdd(&g_sumexp[colBase + t], colS[t]);  // transpose contribution
    }
}

// ---------------------------------------------------------------------------
// Kernel 3: mean(log(sumexp) - pos_logit)
// ---------------------------------------------------------------------------
__global__ void finalize_kernel(float* __restrict__ out) {
    int t = threadIdx.x;
    float acc = 0.0f;
    for (int r = t; r < NROWS; r += 256)
        acc += logf(g_sumexp[r]) - g_pos[r];
    #pragma unroll
    for (int o = 16; o > 0; o >>= 1) acc += __shfl_xor_sync(0xffffffffu, acc, o);
    __shared__ float red[8];
    if ((t & 31) == 0) red[t >> 5] = acc;
    __syncthreads();
    if (t == 0) {
        float s = 0.0f;
        #pragma unroll
        for (int i = 0; i < 8; i++) s += red[i];
        out[0] = s / (float)NROWS;
    }
}

// ---------------------------------------------------------------------------
extern "C" void kernel_launch(void* const* d_in, const int* in_sizes, int n_in,
                              void* d_out, int out_size) {
    const float* zi = (const float*)d_in[0];
    const float* zj = (const float*)d_in[1];
    float* out = (float*)d_out;

    const int smemBytes = 4 * TILEW * (int)sizeof(uint32_t) + 2 * TM * (int)sizeof(float);
    cudaFuncSetAttribute(gram_kernel,
                         cudaFuncAttributeMaxDynamicSharedMemorySize, smemBytes);

    norm_kernel<<<NROWS / 8, 256>>>(zi, zj);
    gram_kernel<<<NCTA, 256, smemBytes>>>();
    finalize_kernel<<<1, 256>>>(out);
}

// round 5
// speedup vs baseline: 12.0805x; 1.0403x over previous
#include <cuda_runtime.h>
#include <cuda_bf16.h>
#include <stdint.h>
#include <math.h>

#define NROWS 8192
#define NHALF 4096
#define DDIM  256
#define TM 128
#define TN 128
#define KC 32
#define NKC (DDIM / KC)                // 8 k-chunks
#define NSTAGE 4
#define STAGE_BYTES 16384              // A 8KB + B 8KB
#define NTILE (NROWS / TM)             // 64
#define NCTA (NTILE * (NTILE + 1) / 2) // 2080
#define SMEM_RED (NSTAGE * STAGE_BYTES)
#define SMEM_TOTAL (SMEM_RED + 2 * TM * 4)
#define INV_T 10.0f

__device__ __align__(16) __nv_bfloat16 g_znh[NROWS * DDIM];
__device__ float g_sumexp[NROWS];
__device__ float g_pos[NROWS];

__device__ __forceinline__ void cp16(uint32_t s, const void* g) {
    asm volatile("cp.async.cg.shared.global [%0], [%1], 16;\n" :: "r"(s), "l"(g));
}
__device__ __forceinline__ void cp_commit() { asm volatile("cp.async.commit_group;\n" ::: "memory"); }
template <int N>
__device__ __forceinline__ void cp_wait() { asm volatile("cp.async.wait_group %0;\n" :: "n"(N) : "memory"); }

__device__ __forceinline__ void ldsm4(uint32_t addr, uint32_t& q0, uint32_t& q1,
                                      uint32_t& q2, uint32_t& q3) {
    asm volatile("ldmatrix.sync.aligned.m8n8.x4.shared.b16 {%0,%1,%2,%3}, [%4];"
                 : "=r"(q0), "=r"(q1), "=r"(q2), "=r"(q3) : "r"(addr));
}

__device__ __forceinline__ void mma16816(float* c, const uint32_t* a, const uint32_t* b) {
    asm volatile(
        "mma.sync.aligned.m16n8k16.row.col.f32.bf16.bf16.f32 "
        "{%0,%1,%2,%3}, {%4,%5,%6,%7}, {%8,%9}, {%0,%1,%2,%3};\n"
        : "+f"(c[0]), "+f"(c[1]), "+f"(c[2]), "+f"(c[3])
        : "r"(a[0]), "r"(a[1]), "r"(a[2]), "r"(a[3]), "r"(b[0]), "r"(b[1]));
}

// ---------------------------------------------------------------------------
// Kernel 1: L2-normalize, emit bf16; re-zero g_sumexp each replay.
// ---------------------------------------------------------------------------
__global__ void norm_kernel(const float* __restrict__ zi,
                            const float* __restrict__ zj) {
    int warp = threadIdx.x >> 5, lane = threadIdx.x & 31;
    int row = blockIdx.x * 8 + warp;
    const float* srcf = (row < NHALF) ? (zi + (size_t)row * DDIM)
                                      : (zj + (size_t)(row - NHALF) * DDIM);
    const float4* src = (const float4*)srcf;
    float4 a = src[lane];
    float4 b = src[lane + 32];
    float ss = a.x*a.x + a.y*a.y + a.z*a.z + a.w*a.w
             + b.x*b.x + b.y*b.y + b.z*b.z + b.w*b.w;
    #pragma unroll
    for (int o = 16; o > 0; o >>= 1) ss += __shfl_xor_sync(0xffffffffu, ss, o);
    float inv = 1.0f / fmaxf(sqrtf(ss), 1e-8f);

    __nv_bfloat162* out = (__nv_bfloat162*)(g_znh + (size_t)row * DDIM);
    out[lane * 2 + 0]      = __floats2bfloat162_rn(a.x * inv, a.y * inv);
    out[lane * 2 + 1]      = __floats2bfloat162_rn(a.z * inv, a.w * inv);
    out[64 + lane * 2 + 0] = __floats2bfloat162_rn(b.x * inv, b.y * inv);
    out[64 + lane * 2 + 1] = __floats2bfloat162_rn(b.z * inv, b.w * inv);
    if (lane == 0) g_sumexp[row] = 0.0f;
}

// ---------------------------------------------------------------------------
// Kernel 2: upper-triangular Gram, bf16 mma.sync + ldmatrix, 4-stage
// cp.async ring (KC=32), fused exp row/col sums. 8 warps as 2(m) x 4(n),
// warp tile 64x32 (4x4 m16n8k16 fragments).
// Smem per stage: A 128x32 + B 128x32 bf16, 64B rows stored as swizzled 16B
// chunks: addr(r, ch) = r*64 + ((ch ^ ((r>>1)&3)) << 4)  -> ldmatrix phases
// hit banks ch' + 4*(r&1), all-distinct per 8-row group.
// ---------------------------------------------------------------------------
__global__ void __launch_bounds__(256, 2) gram_kernel() {
    extern __shared__ char smem[];
    uint32_t smbase = (uint32_t)__cvta_generic_to_shared(smem);
    float* rowS = (float*)(smem + SMEM_RED);
    float* colS = rowS + TM;

    int t = threadIdx.x;
    int bid = blockIdx.x;

    int I = 0;
    while (NTILE * (I + 1) - ((I + 1) * I) / 2 <= bid) I++;
    int J = I + (bid - (NTILE * I - (I * (I - 1)) / 2));
    int rowBase = I * TM, colBase = J * TN;

    if (t < TM) { rowS[t] = 0.0f; colS[t] = 0.0f; }

    int lane = t & 31;
    int g = lane >> 2, c = lane & 3;
    int warp = t >> 5;
    int wm = warp & 1;
    int wn = warp >> 1;

    const char* gz = (const char*)g_znh;

    // cp.async: per stage each thread writes 2 A-chunks + 2 B-chunks.
    // idx in [0,512): r = idx>>2, ch = idx&3.
    auto prefetch = [&](int buf, int kc) {
        uint32_t stA = smbase + buf * STAGE_BYTES;
        uint32_t stB = stA + 8192;
        #pragma unroll
        for (int i = 0; i < 2; i++) {
            int idx = t + i * 256;
            int r = idx >> 2, ch = idx & 3;
            uint32_t soff = (uint32_t)(r * 64 + ((ch ^ ((r >> 1) & 3)) << 4));
            size_t gcol = (size_t)kc * KC + ch * 8;
            cp16(stA + soff, gz + ((size_t)(rowBase + r) * DDIM + gcol) * 2);
            cp16(stB + soff, gz + ((size_t)(colBase + r) * DDIM + gcol) * 2);
        }
        cp_commit();
    };

    // per-lane ldmatrix geometry (loop-invariant)
    int lrow = lane & 15, lh = lane >> 4;
    int sw = (lrow >> 1) & 3;
    uint32_t aRowOff = (uint32_t)((wm * 64 + lrow) * 64);
    uint32_t bRowOff = (uint32_t)((wn * 32 + lrow) * 64);

    float acc[4][4][4] = {};

    prefetch(0, 0);
    prefetch(1, 1);
    prefetch(2, 2);

    #pragma unroll
    for (int kc = 0; kc < NKC; kc++) {
        if (kc < 5) cp_wait<2>(); else cp_wait<0>();
        __syncthreads();
        if (kc + 3 < NKC) prefetch((kc + 3) & 3, kc + 3);

        uint32_t stA = smbase + (kc & 3) * STAGE_BYTES;
        uint32_t stB = stA + 8192;

        #pragma unroll
        for (int ks = 0; ks < 2; ks++) {
            uint32_t chx = (uint32_t)(((ks * 2 + lh) ^ sw) << 4);
            uint32_t a[4][4], b[4][2];
            #pragma unroll
            for (int mt = 0; mt < 4; mt++)
                ldsm4(stA + aRowOff + (uint32_t)(mt * 1024) + chx,
                      a[mt][0], a[mt][1], a[mt][2], a[mt][3]);
            #pragma unroll
            for (int p = 0; p < 2; p++)
                ldsm4(stB + bRowOff + (uint32_t)(p * 1024) + chx,
                      b[2*p][0], b[2*p+1][0], b[2*p][1], b[2*p+1][1]);
            #pragma unroll
            for (int mt = 0; mt < 4; mt++)
                #pragma unroll
                for (int nt = 0; nt < 4; nt++)
                    mma16816(acc[mt][nt], a[mt], b[nt]);
        }
    }

    // ---- epilogue (identical math to round 3) ----
    float rloc[4][2] = {};
    float cloc[4][2] = {};
    bool isPosTile = (colBase == (rowBase ^ NHALF));

    #pragma unroll
    for (int mt = 0; mt < 4; mt++) {
        #pragma unroll
        for (int h = 0; h < 2; h++) {
            int rl = wm * 64 + mt * 16 + g + 8 * h;
            int gi = rowBase + rl;
            #pragma unroll
            for (int nt = 0; nt < 4; nt++) {
                #pragma unroll
                for (int j = 0; j < 2; j++) {
                    int cl = wn * 32 + nt * 8 + 2 * c + j;
                    int gj = colBase + cl;
                    float logit = acc[mt][nt][2 * h + j] * INV_T;
                    if (isPosTile && cl == rl) { g_pos[gi] = logit; g_pos[gj] = logit; }
                    float e = (gi == gj) ? 0.0f : __expf(logit);
                    rloc[mt][h] += e;
                    cloc[nt][j] += e;
                }
            }
        }
    }

    #pragma unroll
    for (int mt = 0; mt < 4; mt++) {
        #pragma unroll
        for (int h = 0; h < 2; h++) {
            float v = rloc[mt][h];
            v += __shfl_xor_sync(0xffffffffu, v, 1);
            v += __shfl_xor_sync(0xffffffffu, v, 2);
            if (c == 0) atomicAdd(&rowS[wm * 64 + mt * 16 + g + 8 * h], v);
        }
    }
    #pragma unroll
    for (int nt = 0; nt < 4; nt++) {
        #pragma unroll
        for (int j = 0; j < 2; j++) {
            float v = cloc[nt][j];
            v += __shfl_xor_sync(0xffffffffu, v, 4);
            v += __shfl_xor_sync(0xffffffffu, v, 8);
            v += __shfl_xor_sync(0xffffffffu, v, 16);
            if (g == 0) atomicAdd(&colS[wn * 32 + nt * 8 + 2 * c + j], v);
        }
    }

    __syncthreads();
    if (t < TM) {
        atomicAdd(&g_sumexp[rowBase + t], rowS[t]);
        if (rowBase != colBase)
            atomicAdd(&g_sumexp[colBase + t], colS[t]);
    }
}

// ---------------------------------------------------------------------------
// Kernel 3: mean(log(sumexp) - pos_logit)
// ---------------------------------------------------------------------------
__global__ void finalize_kernel(float* __restrict__ out) {
    int t = threadIdx.x;
    float acc = 0.0f;
    for (int r = t; r < NROWS; r += 256)
        acc += logf(g_sumexp[r]) - g_pos[r];
    #pragma unroll
    for (int o = 16; o > 0; o >>= 1) acc += __shfl_xor_sync(0xffffffffu, acc, o);
    __shared__ float red[8];
    if ((t & 31) == 0) red[t >> 5] = acc;
    __syncthreads();
    if (t == 0) {
        float s = 0.0f;
        #pragma unroll
        for (int i = 0; i < 8; i++) s += red[i];
        out[0] = s / (float)NROWS;
    }
}

// ---------------------------------------------------------------------------
extern "C" void kernel_launch(void* const* d_in, const int* in_sizes, int n_in,
                              void* d_out, int out_size) {
    const float* zi = (const float*)d_in[0];
    const float* zj = (const float*)d_in[1];
    float* out = (float*)d_out;

    cudaFuncSetAttribute(gram_kernel,
                         cudaFuncAttributeMaxDynamicSharedMemorySize, SMEM_TOTAL);

    norm_kernel<<<NROWS / 8, 256>>>(zi, zj);
    gram_kernel<<<NCTA, 256, SMEM_TOTAL>>>();
    finalize_kernel<<<1, 256>>>(out);
}